// round 5
// baseline (speedup 1.0000x reference)
#include <cuda_runtime.h>
#include <math.h>
#include <stdint.h>

#define BW 64
#define BO 64
#define TW 32
#define TO 36
#define DD 512
#define SCALE 0.044194173824159216f  // 1/sqrt(512)
#define WSTR 520                     // w row stride (floats)
#define OSTR 516                     // u/o row stride (floats)
#define NTHR 576

// smem layout (float offsets)
#define OFF_W     0          // 32*520 = 16640
#define OFF_UO    16640      // 36*516+4 -> 18592
#define OFF_SCR   35232      // 32*37 = 1184
#define OFF_ATTC  36416      // 1168
#define OFF_ATTAL 37584      // 32*36 = 1152 (aligned att copy)
#define OFF_LGP   38736      // 64
#define OFF_LGP2  38800      // 128
#define OFF_PMAX  38928      // 288
#define OFF_PSUM  39216      // 288
#define OFF_RMAX  39504      // 32
#define OFF_RINV  39536      // 32
#define SMEM_FLOATS 39568    // 158272 bytes

__device__ float g_logits[BW * TW * BO];   // [wb][t][ob]
__device__ float g_partial[BW];

typedef unsigned long long ull;

__device__ __forceinline__ void fma2(ull &d, ull a, ull b) {
    asm("fma.rn.f32x2 %0, %1, %2, %0;" : "+l"(d) : "l"(a), "l"(b));
}
__device__ __forceinline__ ull pack2(float a) {
    ull r; asm("mov.b64 %0, {%1, %1};" : "=l"(r) : "f"(a)); return r;
}

union F4U { float4 f; ull u[2]; float s[4]; };
union U2F { ull u; float2 f; };

__device__ __forceinline__ float hsum2(ull a) {
    U2F t; t.u = a; return t.f.x + t.f.y;
}

extern __shared__ float smem[];

__global__ __launch_bounds__(NTHR, 1)
void cap_main(const float* __restrict__ g_o,
              const float* __restrict__ g_u,
              const float* __restrict__ g_w,
              float* __restrict__ out_att,   // = d_out + 1
              float* __restrict__ out_avo)   // = d_out + 1 + 64*64*32*36
{
    const int ob  = blockIdx.x;
    const int wb  = blockIdx.y;
    const int blk = wb * BO + ob;
    const int tid = threadIdx.x;

    float*  w_s    = smem + OFF_W;
    float*  uo     = smem + OFF_UO;
    float*  scr    = smem + OFF_SCR;
    float*  att_cs = smem + OFF_ATTC;
    float*  att_al = smem + OFF_ATTAL;
    float*  lgp    = smem + OFF_LGP;
    float*  lgp2   = smem + OFF_LGP2;
    float*  pmax   = smem + OFF_PMAX;
    float*  psum   = smem + OFF_PSUM;
    float*  rowmax = smem + OFF_RMAX;
    float*  rowinv = smem + OFF_RINV;

    // ---------- phase 1: load w (32x512, stride 520) and u (36x512, 516) ----
    for (int idx = tid; idx < TW * 128; idx += NTHR) {
        int t = idx >> 7, c = idx & 127;
        float4 v = reinterpret_cast<const float4*>(g_w)[((size_t)wb * TW + t) * 128 + c];
        *reinterpret_cast<float4*>(&w_s[t * WSTR + 4 * c]) = v;
    }
    for (int idx = tid; idx < TO * 128; idx += NTHR) {
        int o = idx >> 7, c = idx & 127;
        float4 v = reinterpret_cast<const float4*>(g_u)[((size_t)ob * TO + o) * 128 + c];
        *reinterpret_cast<float4*>(&uo[o * OSTR + 4 * c]) = v;
    }
    __syncthreads();

    // ---------- phase 2: scores, 8t x 4o tile, 16 d-slices in lane bits -----
    // tg = grp/9 so both half-warps of a warp share the t-octet (broadcast w)
    {
        const int dq  = tid & 15;          // d-slice (lane bits 0-3)
        const int grp = tid >> 4;          // 0..35
        const int og  = grp % 9;           // o base = og*4
        const int tg  = grp / 9;           // t base = tg*8

        const float* wbase = w_s + (tg * 8) * WSTR + 4 * dq;
        const float* ubase = uo  + (og * 4) * OSTR + 4 * dq;

        ull acc[8][4];
        #pragma unroll
        for (int i = 0; i < 8; i++)
            #pragma unroll
            for (int j = 0; j < 4; j++) acc[i][j] = 0ULL;

        #pragma unroll
        for (int cc = 0; cc < 8; cc++) {   // c = 16*cc + dq
            F4U uv[4];
            #pragma unroll
            for (int j = 0; j < 4; j++)
                uv[j].f = *reinterpret_cast<const float4*>(&ubase[j * OSTR + cc * 64]);
            #pragma unroll
            for (int i = 0; i < 8; i++) {
                F4U wv;
                wv.f = *reinterpret_cast<const float4*>(&wbase[i * WSTR + cc * 64]);
                #pragma unroll
                for (int j = 0; j < 4; j++) {
                    fma2(acc[i][j], wv.u[0], uv[j].u[0]);
                    fma2(acc[i][j], wv.u[1], uv[j].u[1]);
                }
            }
        }

        float sums[32];
        #pragma unroll
        for (int i = 0; i < 8; i++)
            #pragma unroll
            for (int j = 0; j < 4; j++) sums[i * 4 + j] = hsum2(acc[i][j]);

        #pragma unroll
        for (int s = 1; s < 16; s <<= 1)
            #pragma unroll
            for (int k = 0; k < 32; k++)
                sums[k] += __shfl_xor_sync(0xffffffffu, sums[k], s);

        #pragma unroll
        for (int e = 0; e < 2; e++) {
            int k = 2 * dq + e;
            int i = k >> 2, j = k & 3;
            scr[(tg * 8 + i) * 37 + og * 4 + j] = sums[k];
        }
    }
    __syncthreads();

    // ---------- phase 3: softmax over To=36 per t row -----------------------
    const int st = tid / 9, sj = tid % 9;      // valid for tid<288
    float sc[4], ee[4];
    if (tid < 288) {
        #pragma unroll
        for (int q = 0; q < 4; q++)
            sc[q] = scr[st * 37 + 4 * sj + q] * SCALE;
        pmax[tid] = fmaxf(fmaxf(sc[0], sc[1]), fmaxf(sc[2], sc[3]));
    }
    __syncthreads();
    if (tid < 32) {
        float m = pmax[tid * 9];
        #pragma unroll
        for (int k = 1; k < 9; k++) m = fmaxf(m, pmax[tid * 9 + k]);
        rowmax[tid] = m;
    }
    __syncthreads();
    if (tid < 288) {
        float m = rowmax[st];
        float s = 0.f;
        #pragma unroll
        for (int q = 0; q < 4; q++) { ee[q] = expf(sc[q] - m); s += ee[q]; }
        psum[tid] = s;
    }
    __syncthreads();
    if (tid < 32) {
        float s = 0.f;
        #pragma unroll
        for (int k = 0; k < 9; k++) s += psum[tid * 9 + k];
        rowinv[tid] = 1.f / s;
    }
    __syncthreads();
    if (tid < 288) {
        float inv = rowinv[st];
        #pragma unroll
        for (int q = 0; q < 4; q++) {
            float a = ee[q] * inv;
            int idx = st * TO + 4 * sj + q;
            att_cs[1 + idx] = a;
            att_al[idx]     = a;
        }
    }
    __syncthreads();

    // ---------- att store (shifted float4) + phase 4a: o tile (shift +1) ----
    {
        const size_t ab = (size_t)blk * (TW * TO);
        if (tid < 287) {
            float4 v = *reinterpret_cast<const float4*>(&att_cs[4 + 4 * tid]);
            *reinterpret_cast<float4*>(&out_att[ab + 3 + 4 * tid]) = v;
        } else if (tid == 287) {
            out_att[ab + 0]    = att_cs[1];
            out_att[ab + 1]    = att_cs[2];
            out_att[ab + 2]    = att_cs[3];
            out_att[ab + 1151] = att_cs[1152];
        }
    }
    for (int task = tid; task < TO * 127; task += NTHR) {
        int o = task / 127, k = task % 127;
        const float* gr = g_o + ((size_t)ob * TO + o) * 512;
        float4 A  = *reinterpret_cast<const float4*>(&gr[4 * k]);
        float4 Bv = *reinterpret_cast<const float4*>(&gr[4 * k + 4]);
        *reinterpret_cast<float4*>(&uo[o * OSTR + 4 + 4 * k]) =
            make_float4(A.w, Bv.x, Bv.y, Bv.z);
    }
    if (tid < 144) {
        int o = tid / 4, e = tid % 4;
        const float* gr = g_o + ((size_t)ob * TO + o) * 512;
        if (e < 3) uo[o * OSTR + 1 + e] = gr[e];
        else       uo[o * OSTR + 512]   = gr[511];
    }
    __syncthreads();

    // ---------- phase 4b: att_V_o; warp = t-quad, lanes = windows -----------
    const int wrp  = tid >> 5;
    const int lane = tid & 31;
    if (wrp < 16) {
        const int quad = wrp & 7;          // t = quad*4 + i
        const int half = wrp >> 3;
        const int k1 = half * 64 + lane;
        const int k2 = k1 + 32;
        const bool have2 = (k2 < 127);

        const float* ow1 = &uo[4 + 4 * k1];
        const float* ow2 = &uo[4 + 4 * k2];
        const float* attp = att_al + (quad * 4) * TO;

        ull a1[4][2], a2[4][2];
        #pragma unroll
        for (int i = 0; i < 4; i++) {
            a1[i][0] = a1[i][1] = 0ULL;
            a2[i][0] = a2[i][1] = 0ULL;
        }

        #pragma unroll
        for (int ob4 = 0; ob4 < 9; ob4++) {
            F4U av[4];
            #pragma unroll
            for (int i = 0; i < 4; i++)
                av[i].f = *reinterpret_cast<const float4*>(&attp[i * TO + 4 * ob4]);
            #pragma unroll
            for (int oo = 0; oo < 4; oo++) {
                const int o = 4 * ob4 + oo;
                F4U ov1; ov1.f = *reinterpret_cast<const float4*>(&ow1[o * OSTR]);
                F4U ov2; ov2.f = *reinterpret_cast<const float4*>(&ow2[o * OSTR]);
                #pragma unroll
                for (int i = 0; i < 4; i++) {
                    ull aa = pack2(av[i].s[oo]);
                    fma2(a1[i][0], aa, ov1.u[0]);
                    fma2(a1[i][1], aa, ov1.u[1]);
                    fma2(a2[i][0], aa, ov2.u[0]);
                    fma2(a2[i][1], aa, ov2.u[1]);
                }
            }
        }

        float lg[4];
        #pragma unroll
        for (int i = 0; i < 4; i++) {
            const int t = 4 * quad + i;
            const size_t tb = ((size_t)blk * TW + t) * DD;
            {
                F4U av; av.u[0] = a1[i][0]; av.u[1] = a1[i][1];
                *reinterpret_cast<float4*>(&out_avo[tb + 3 + 4 * k1]) = av.f;
                F4U wA; wA.f = *reinterpret_cast<const float4*>(&w_s[t * WSTR + 4 * k1]);
                F4U wB; wB.f = *reinterpret_cast<const float4*>(&w_s[t * WSTR + 4 * k1 + 4]);
                lg[i] = av.s[0] * wA.s[3] + av.s[1] * wB.s[0]
                      + av.s[2] * wB.s[1] + av.s[3] * wB.s[2];
            }
            if (have2) {
                F4U av; av.u[0] = a2[i][0]; av.u[1] = a2[i][1];
                *reinterpret_cast<float4*>(&out_avo[tb + 3 + 4 * k2]) = av.f;
                F4U wA; wA.f = *reinterpret_cast<const float4*>(&w_s[t * WSTR + 4 * k2]);
                F4U wB; wB.f = *reinterpret_cast<const float4*>(&w_s[t * WSTR + 4 * k2 + 4]);
                lg[i] += av.s[0] * wA.s[3] + av.s[1] * wB.s[0]
                       + av.s[2] * wB.s[1] + av.s[3] * wB.s[2];
            }
        }
        #pragma unroll
        for (int s = 16; s; s >>= 1)
            #pragma unroll
            for (int i = 0; i < 4; i++)
                lg[i] += __shfl_xor_sync(0xffffffffu, lg[i], s);
        if (lane == 0) {
            #pragma unroll
            for (int i = 0; i < 4; i++)
                lgp[(4 * quad + i) * 2 + half] = lg[i];
        }
    } else {
        // warps 16-17: edge columns d in {0,1,2,511}, 2 tasks/thread
        const int base = tid - 512;
        #pragma unroll
        for (int rep = 0; rep < 2; rep++) {
            int task = base + 64 * rep;
            int t = task >> 2, e = task & 3;
            int d    = (e < 3) ? e       : 511;
            int soff = (e < 3) ? (1 + e) : 512;
            float acc = 0.f;
            #pragma unroll 4
            for (int o = 0; o < TO; o++)
                acc += att_al[t * TO + o] * uo[o * OSTR + soff];
            out_avo[((size_t)blk * TW + t) * DD + d] = acc;
            lgp2[task] = acc * w_s[t * WSTR + d];
        }
    }
    __syncthreads();

    if (tid < 32) {
        float s = lgp[tid * 2] + lgp[tid * 2 + 1];
        #pragma unroll
        for (int e = 0; e < 4; e++) s += lgp2[tid * 4 + e];
        g_logits[(wb * TW + tid) * BO + ob] = s;
    }
}

// log-softmax over Bo + masked diagonal accumulation, one block per wb
__global__ void cap_loss1(const int* __restrict__ g_mask)
{
    const int wb   = blockIdx.x;
    const int wid  = threadIdx.x >> 5;
    const int lane = threadIdx.x & 31;
    __shared__ float warp_part[8];

    float keepl = 1.f - (float)g_mask[wb * TW + lane];
    float nk = keepl;
    #pragma unroll
    for (int s = 16; s; s >>= 1) nk += __shfl_xor_sync(0xffffffffu, nk, s);

    float acc = 0.f;
    #pragma unroll
    for (int k = 0; k < 4; k++) {
        int t = wid + 8 * k;
        const float* row = g_logits + (wb * TW + t) * BO;
        float v0 = row[lane], v1 = row[lane + 32];
        float m = fmaxf(v0, v1);
        #pragma unroll
        for (int s = 16; s; s >>= 1) m = fmaxf(m, __shfl_xor_sync(0xffffffffu, m, s));
        float e = expf(v0 - m) + expf(v1 - m);
        #pragma unroll
        for (int s = 16; s; s >>= 1) e += __shfl_xor_sync(0xffffffffu, e, s);
        float lse = m + logf(e);
        float dv = (wb < 32) ? __shfl_sync(0xffffffffu, v0, wb)
                             : __shfl_sync(0xffffffffu, v1, wb - 32);
        float kt = 1.f - (float)g_mask[wb * TW + t];
        acc += kt * (dv - lse);
    }
    if (lane == 0) warp_part[wid] = acc;
    __syncthreads();
    if (threadIdx.x == 0) {
        float s = 0.f;
        #pragma unroll
        for (int k = 0; k < 8; k++) s += warp_part[k];
        g_partial[wb] = s / (nk + 1e-6f);
    }
}

__global__ void cap_loss2(float* __restrict__ out)
{
    __shared__ float sh[64];
    sh[threadIdx.x] = g_partial[threadIdx.x];
    __syncthreads();
    if (threadIdx.x == 0) {
        float s = 0.f;
        #pragma unroll
        for (int k = 0; k < 64; k++) s += sh[k];
        out[0] = -s / 64.f;
    }
}

extern "C" void kernel_launch(void* const* d_in, const int* in_sizes, int n_in,
                              void* d_out, int out_size)
{
    const float* g_o    = (const float*)d_in[0];
    const float* g_u    = (const float*)d_in[1];
    const float* g_w    = (const float*)d_in[2];
    const int*   g_mask = (const int*)d_in[3];

    float* out     = (float*)d_out;
    float* out_att = out + 1;
    float* out_avo = out_att + (size_t)BW * BO * TW * TO;

    const size_t SMEM_BYTES = (size_t)SMEM_FLOATS * sizeof(float);
    cudaFuncSetAttribute(cap_main, cudaFuncAttributeMaxDynamicSharedMemorySize,
                         (int)SMEM_BYTES);

    dim3 grid(BO, BW);
    cap_main<<<grid, NTHR, SMEM_BYTES>>>(g_o, g_u, g_w, out_att, out_avo);
    cap_loss1<<<BW, 256>>>(g_mask);
    cap_loss2<<<1, 64>>>(out);
}

// round 6
// speedup vs baseline: 1.5338x; 1.5338x over previous
#include <cuda_runtime.h>
#include <math.h>
#include <stdint.h>

#define BW 64
#define BO 64
#define TW 32
#define TO 36
#define DD 512
#define SCALE 0.044194173824159216f  // 1/sqrt(512)
#define WSTR 520                     // w row stride (floats)
#define OSTR 516                     // u/o row stride (floats)
#define NTHR 576

// smem layout (float offsets)  — R4 layout + aligned att copy appended
#define OFF_W    0          // 32*520 = 16640
#define OFF_UO   16640      // 36*516+4 -> 18592
#define OFF_SCR  35232      // 32*37 = 1184
#define OFF_ATTC 36416      // 1168
#define OFF_LGP  37584      // 32*72 = 2304
#define OFF_LGP2 39888      // 128
#define OFF_PMAX 40016      // 288
#define OFF_PSUM 40304      // 288
#define OFF_RMAX 40592      // 32
#define OFF_RINV 40624      // 32
#define OFF_ATTAL 40656     // 32*36 = 1152 (16B-aligned att copy)
#define SMEM_FLOATS 41808   // 167232 bytes

__device__ float g_logits[BW * TW * BO];   // [wb][t][ob]
__device__ float g_partial[BW];

typedef unsigned long long ull;

__device__ __forceinline__ void fma2(ull &d, ull a, ull b) {
    asm("fma.rn.f32x2 %0, %1, %2, %0;" : "+l"(d) : "l"(a), "l"(b));
}
__device__ __forceinline__ ull pack2(float a) {
    ull r; asm("mov.b64 %0, {%1, %1};" : "=l"(r) : "f"(a)); return r;
}

union F4U { float4 f; ull u[2]; float s[4]; };
union U2F { ull u; float2 f; };

__device__ __forceinline__ float hsum2(ull a) {
    U2F t; t.u = a; return t.f.x + t.f.y;
}

extern __shared__ float smem[];

__global__ __launch_bounds__(NTHR, 1)
void cap_main(const float* __restrict__ g_o,
              const float* __restrict__ g_u,
              const float* __restrict__ g_w,
              float* __restrict__ out_att,   // = d_out + 1
              float* __restrict__ out_avo)   // = d_out + 1 + 64*64*32*36
{
    const int ob  = blockIdx.x;
    const int wb  = blockIdx.y;
    const int blk = wb * BO + ob;
    const int tid = threadIdx.x;

    float*  w_s    = smem + OFF_W;
    float*  uo     = smem + OFF_UO;
    float*  scr    = smem + OFF_SCR;
    float*  att_cs = smem + OFF_ATTC;
    float*  att_al = smem + OFF_ATTAL;
    float*  lgp    = smem + OFF_LGP;
    float*  lgp2   = smem + OFF_LGP2;
    float*  pmax   = smem + OFF_PMAX;
    float*  psum   = smem + OFF_PSUM;
    float*  rowmax = smem + OFF_RMAX;
    float*  rowinv = smem + OFF_RINV;

    // ---------- phase 1: load w (32x512, stride 520) and u (36x512, 516) ----
    for (int idx = tid; idx < TW * 128; idx += NTHR) {
        int t = idx >> 7, c = idx & 127;
        float4 v = reinterpret_cast<const float4*>(g_w)[((size_t)wb * TW + t) * 128 + c];
        *reinterpret_cast<float4*>(&w_s[t * WSTR + 4 * c]) = v;
    }
    for (int idx = tid; idx < TO * 128; idx += NTHR) {
        int o = idx >> 7, c = idx & 127;
        float4 v = reinterpret_cast<const float4*>(g_u)[((size_t)ob * TO + o) * 128 + c];
        *reinterpret_cast<float4*>(&uo[o * OSTR + 4 * c]) = v;
    }
    __syncthreads();

    // ---------- phase 2: scores, 8t x 4o tile, 16 d-slices in lane bits -----
    {
        const int dq  = tid & 15;          // d-slice (lane bits 0-3)
        const int grp = tid >> 4;          // 0..35
        const int tg  = grp & 3;           // t base = tg*8
        const int og  = grp >> 2;          // 0..8 -> o base = og*4

        const float* wbase = w_s + (tg * 8) * WSTR + 4 * dq;
        const float* ubase = uo  + (og * 4) * OSTR + 4 * dq;

        ull acc[8][4];
        #pragma unroll
        for (int i = 0; i < 8; i++)
            #pragma unroll
            for (int j = 0; j < 4; j++) acc[i][j] = 0ULL;

        #pragma unroll
        for (int cc = 0; cc < 8; cc++) {   // c = 16*cc + dq
            F4U uv[4];
            #pragma unroll
            for (int j = 0; j < 4; j++)
                uv[j].f = *reinterpret_cast<const float4*>(&ubase[j * OSTR + cc * 64]);
            #pragma unroll
            for (int i = 0; i < 8; i++) {
                F4U wv;
                wv.f = *reinterpret_cast<const float4*>(&wbase[i * WSTR + cc * 64]);
                #pragma unroll
                for (int j = 0; j < 4; j++) {
                    fma2(acc[i][j], wv.u[0], uv[j].u[0]);
                    fma2(acc[i][j], wv.u[1], uv[j].u[1]);
                }
            }
        }

        float sums[32];
        #pragma unroll
        for (int i = 0; i < 8; i++)
            #pragma unroll
            for (int j = 0; j < 4; j++) sums[i * 4 + j] = hsum2(acc[i][j]);

        #pragma unroll
        for (int s = 1; s < 16; s <<= 1)
            #pragma unroll
            for (int k = 0; k < 32; k++)
                sums[k] += __shfl_xor_sync(0xffffffffu, sums[k], s);

        // all 16 dq lanes now hold the full 32 sums; each stores 2
        #pragma unroll
        for (int e = 0; e < 2; e++) {
            int k = 2 * dq + e;
            int i = k >> 2, j = k & 3;
            scr[(tg * 8 + i) * 37 + og * 4 + j] = sums[k];
        }
    }
    __syncthreads();

    // ---------- phase 3: softmax over To=36 per t row -----------------------
    const int st = tid / 9, sj = tid % 9;      // valid for tid<288
    float sc[4], ee[4];
    if (tid < 288) {
        #pragma unroll
        for (int q = 0; q < 4; q++)
            sc[q] = scr[st * 37 + 4 * sj + q] * SCALE;
        pmax[tid] = fmaxf(fmaxf(sc[0], sc[1]), fmaxf(sc[2], sc[3]));
    }
    __syncthreads();
    if (tid < 32) {
        float m = pmax[tid * 9];
        #pragma unroll
        for (int k = 1; k < 9; k++) m = fmaxf(m, pmax[tid * 9 + k]);
        rowmax[tid] = m;
    }
    __syncthreads();
    if (tid < 288) {
        float m = rowmax[st];
        float s = 0.f;
        #pragma unroll
        for (int q = 0; q < 4; q++) { ee[q] = expf(sc[q] - m); s += ee[q]; }
        psum[tid] = s;
    }
    __syncthreads();
    if (tid < 32) {
        float s = 0.f;
        #pragma unroll
        for (int k = 0; k < 9; k++) s += psum[tid * 9 + k];
        rowinv[tid] = 1.f / s;
    }
    __syncthreads();
    if (tid < 288) {
        float inv = rowinv[st];
        #pragma unroll
        for (int q = 0; q < 4; q++) {
            float a = ee[q] * inv;
            int idx = st * TO + 4 * sj + q;
            att_cs[1 + idx] = a;
            att_al[idx]     = a;
        }
    }
    __syncthreads();

    // ---------- att store (shifted float4) + phase 4a: o tile (shift +1) ----
    {
        const size_t ab = (size_t)blk * (TW * TO);
        if (tid < 287) {
            float4 v = *reinterpret_cast<const float4*>(&att_cs[4 + 4 * tid]);
            *reinterpret_cast<float4*>(&out_att[ab + 3 + 4 * tid]) = v;
        } else if (tid == 287) {
            out_att[ab + 0]    = att_cs[1];
            out_att[ab + 1]    = att_cs[2];
            out_att[ab + 2]    = att_cs[3];
            out_att[ab + 1151] = att_cs[1152];
        }
    }
    for (int task = tid; task < TO * 127; task += NTHR) {
        int o = task / 127, k = task % 127;
        const float* gr = g_o + ((size_t)ob * TO + o) * 512;
        float4 A  = *reinterpret_cast<const float4*>(&gr[4 * k]);
        float4 Bv = *reinterpret_cast<const float4*>(&gr[4 * k + 4]);
        *reinterpret_cast<float4*>(&uo[o * OSTR + 4 + 4 * k]) =
            make_float4(A.w, Bv.x, Bv.y, Bv.z);
    }
    if (tid < 144) {
        int o = tid / 4, e = tid % 4;
        const float* gr = g_o + ((size_t)ob * TO + o) * 512;
        if (e < 3) uo[o * OSTR + 1 + e] = gr[e];
        else       uo[o * OSTR + 512]   = gr[511];
    }
    __syncthreads();

    // ---------- phase 4b: att_V_o, o-outer, vectorized att staging ----------
    {
        const int tg4 = tid / 72;          // t = 4*tg4 + i
        const int jj  = tid % 72;
        const bool have2 = (jj <= 54);     // k1 = jj+72 <= 126 valid
        const int k0 = jj;
        const int k1 = have2 ? (jj + 72) : 126;

        const float* ow0 = &uo[4 + 4 * k0];
        const float* ow1 = &uo[4 + 4 * k1];
        const float* attp = att_al + (tg4 * 4) * TO;

        ull a0[4][2], a1[4][2];
        #pragma unroll
        for (int i = 0; i < 4; i++) {
            a0[i][0] = a0[i][1] = 0ULL;
            a1[i][0] = a1[i][1] = 0ULL;
        }

        F4U avv[4];
        #pragma unroll 4
        for (int o = 0; o < TO; o++) {
            if ((o & 3) == 0) {
                #pragma unroll
                for (int i = 0; i < 4; i++)
                    avv[i].f = *reinterpret_cast<const float4*>(&attp[i * TO + o]);
            }
            F4U ov0; ov0.f = *reinterpret_cast<const float4*>(&ow0[o * OSTR]);
            F4U ov1; ov1.f = *reinterpret_cast<const float4*>(&ow1[o * OSTR]);
            #pragma unroll
            for (int i = 0; i < 4; i++) {
                ull aa = pack2(avv[i].s[o & 3]);
                fma2(a0[i][0], aa, ov0.u[0]);
                fma2(a0[i][1], aa, ov0.u[1]);
                fma2(a1[i][0], aa, ov1.u[0]);
                fma2(a1[i][1], aa, ov1.u[1]);
            }
        }

        #pragma unroll
        for (int i = 0; i < 4; i++) {
            const int t = 4 * tg4 + i;
            const size_t tb = ((size_t)blk * TW + t) * DD;
            float lg;
            {
                F4U av; av.u[0] = a0[i][0]; av.u[1] = a0[i][1];
                *reinterpret_cast<float4*>(&out_avo[tb + 3 + 4 * k0]) = av.f;
                F4U wA; wA.f = *reinterpret_cast<const float4*>(&w_s[t * WSTR + 4 * k0]);
                F4U wB; wB.f = *reinterpret_cast<const float4*>(&w_s[t * WSTR + 4 * k0 + 4]);
                lg = av.s[0] * wA.s[3] + av.s[1] * wB.s[0]
                   + av.s[2] * wB.s[1] + av.s[3] * wB.s[2];
            }
            if (have2) {
                F4U av; av.u[0] = a1[i][0]; av.u[1] = a1[i][1];
                *reinterpret_cast<float4*>(&out_avo[tb + 3 + 4 * k1]) = av.f;
                F4U wA; wA.f = *reinterpret_cast<const float4*>(&w_s[t * WSTR + 4 * k1]);
                F4U wB; wB.f = *reinterpret_cast<const float4*>(&w_s[t * WSTR + 4 * k1 + 4]);
                lg += av.s[0] * wA.s[3] + av.s[1] * wB.s[0]
                    + av.s[2] * wB.s[1] + av.s[3] * wB.s[2];
            }
            lgp[t * 72 + jj] = lg;
        }
    }
    // edge columns d in {0,1,2,511} for every t row
    if (tid < 128) {
        int t = tid / 4, e = tid % 4;
        int d    = (e < 3) ? e        : 511;
        int soff = (e < 3) ? (1 + e)  : 512;
        float acc = 0.f;
        #pragma unroll 4
        for (int o = 0; o < TO; o++)
            acc += att_al[t * TO + o] * uo[o * OSTR + soff];
        out_avo[((size_t)blk * TW + t) * DD + d] = acc;
        lgp2[tid] = acc * w_s[t * WSTR + d];
    }
    __syncthreads();

    if (tid < 32) {
        float s = 0.f;
        #pragma unroll
        for (int k = 0; k < 72; k++) s += lgp[tid * 72 + k];
        #pragma unroll
        for (int e = 0; e < 4; e++)  s += lgp2[tid * 4 + e];
        g_logits[(wb * TW + tid) * BO + ob] = s;
    }
}

// log-softmax over Bo + masked diagonal accumulation, one block per wb
__global__ void cap_loss1(const int* __restrict__ g_mask)
{
    const int wb   = blockIdx.x;
    const int wid  = threadIdx.x >> 5;
    const int lane = threadIdx.x & 31;
    __shared__ float warp_part[8];

    float keepl = 1.f - (float)g_mask[wb * TW + lane];
    float nk = keepl;
    #pragma unroll
    for (int s = 16; s; s >>= 1) nk += __shfl_xor_sync(0xffffffffu, nk, s);

    float acc = 0.f;
    #pragma unroll
    for (int k = 0; k < 4; k++) {
        int t = wid + 8 * k;
        const float* row = g_logits + (wb * TW + t) * BO;
        float v0 = row[lane], v1 = row[lane + 32];
        float m = fmaxf(v0, v1);
        #pragma unroll
        for (int s = 16; s; s >>= 1) m = fmaxf(m, __shfl_xor_sync(0xffffffffu, m, s));
        float e = expf(v0 - m) + expf(v1 - m);
        #pragma unroll
        for (int s = 16; s; s >>= 1) e += __shfl_xor_sync(0xffffffffu, e, s);
        float lse = m + logf(e);
        float dv = (wb < 32) ? __shfl_sync(0xffffffffu, v0, wb)
                             : __shfl_sync(0xffffffffu, v1, wb - 32);
        float kt = 1.f - (float)g_mask[wb * TW + t];
        acc += kt * (dv - lse);
    }
    if (lane == 0) warp_part[wid] = acc;
    __syncthreads();
    if (threadIdx.x == 0) {
        float s = 0.f;
        #pragma unroll
        for (int k = 0; k < 8; k++) s += warp_part[k];
        g_partial[wb] = s / (nk + 1e-6f);
    }
}

__global__ void cap_loss2(float* __restrict__ out)
{
    __shared__ float sh[64];
    sh[threadIdx.x] = g_partial[threadIdx.x];
    __syncthreads();
    if (threadIdx.x == 0) {
        float s = 0.f;
        #pragma unroll
        for (int k = 0; k < 64; k++) s += sh[k];
        out[0] = -s / 64.f;
    }
}

extern "C" void kernel_launch(void* const* d_in, const int* in_sizes, int n_in,
                              void* d_out, int out_size)
{
    const float* g_o    = (const float*)d_in[0];
    const float* g_u    = (const float*)d_in[1];
    const float* g_w    = (const float*)d_in[2];
    const int*   g_mask = (const int*)d_in[3];

    float* out     = (float*)d_out;
    float* out_att = out + 1;
    float* out_avo = out_att + (size_t)BW * BO * TW * TO;

    const size_t SMEM_BYTES = (size_t)SMEM_FLOATS * sizeof(float);
    cudaFuncSetAttribute(cap_main, cudaFuncAttributeMaxDynamicSharedMemorySize,
                         (int)SMEM_BYTES);

    dim3 grid(BO, BW);
    cap_main<<<grid, NTHR, SMEM_BYTES>>>(g_o, g_u, g_w, out_att, out_avo);
    cap_loss1<<<BW, 256>>>(g_mask);
    cap_loss2<<<1, 64>>>(out);
}

// round 7
// speedup vs baseline: 1.6356x; 1.0664x over previous
#include <cuda_runtime.h>
#include <math.h>
#include <stdint.h>

#define BW 64
#define BO 64
#define TW 32
#define TO 36
#define DD 512
#define SCALE 0.044194173824159216f  // 1/sqrt(512)
#define WSTR 516                     // w row stride (floats), ≡4 mod 32
#define OSTR 516                     // u/o row stride (floats)
#define NTHR 576

// smem layout (float offsets)
#define OFF_W     0          // 32*516 = 16512
#define OFF_UO    16512      // 40*516 = 20640 (rows 36-39 zero pad for mma)
#define OFF_P2    37152      // 8*1280 = 10240 (mma partials: [ks][32][40])
#define OFF_ATTC  47392      // 1168
#define OFF_ATTAL 48560      // 1152
#define OFF_LGP   49712      // 2304
#define OFF_LGP2  52016      // 128
#define OFF_PMAX  52144      // 288
#define OFF_PSUM  52432      // 288
#define OFF_RMAX  52720      // 32
#define OFF_RINV  52752      // 32
#define SMEM_FLOATS 52784    // 211136 bytes

__device__ float g_logits[BW * TW * BO];   // [wb][t][ob]
__device__ float g_partial[BW];

typedef unsigned long long ull;

__device__ __forceinline__ void fma2(ull &d, ull a, ull b) {
    asm("fma.rn.f32x2 %0, %1, %2, %0;" : "+l"(d) : "l"(a), "l"(b));
}
__device__ __forceinline__ ull pack2(float a) {
    ull r; asm("mov.b64 %0, {%1, %1};" : "=l"(r) : "f"(a)); return r;
}
__device__ __forceinline__ uint32_t f2tf(float x) {
    uint32_t r; asm("cvt.rna.tf32.f32 %0, %1;" : "=r"(r) : "f"(x)); return r;
}
__device__ __forceinline__ void mma_tf32(float* c, const uint32_t* a,
                                         uint32_t b0, uint32_t b1) {
    asm("mma.sync.aligned.m16n8k8.row.col.f32.tf32.tf32.f32 "
        "{%0,%1,%2,%3}, {%4,%5,%6,%7}, {%8,%9}, {%0,%1,%2,%3};"
        : "+f"(c[0]), "+f"(c[1]), "+f"(c[2]), "+f"(c[3])
        : "r"(a[0]), "r"(a[1]), "r"(a[2]), "r"(a[3]), "r"(b0), "r"(b1));
}

union F4U { float4 f; ull u[2]; float s[4]; };

extern __shared__ float smem[];

__global__ __launch_bounds__(NTHR, 1)
void cap_main(const float* __restrict__ g_o,
              const float* __restrict__ g_u,
              const float* __restrict__ g_w,
              float* __restrict__ out_att,   // = d_out + 1
              float* __restrict__ out_avo)   // = d_out + 1 + 64*64*32*36
{
    const int ob  = blockIdx.x;
    const int wb  = blockIdx.y;
    const int blk = wb * BO + ob;
    const int tid = threadIdx.x;

    float*  w_s    = smem + OFF_W;
    float*  uo     = smem + OFF_UO;
    float*  p2     = smem + OFF_P2;
    float*  att_cs = smem + OFF_ATTC;
    float*  att_al = smem + OFF_ATTAL;
    float*  lgp    = smem + OFF_LGP;
    float*  lgp2   = smem + OFF_LGP2;
    float*  pmax   = smem + OFF_PMAX;
    float*  psum   = smem + OFF_PSUM;
    float*  rowmax = smem + OFF_RMAX;
    float*  rowinv = smem + OFF_RINV;

    // ---------- phase 1: load w (32x512) and u (36x512); zero u pad rows ----
    for (int idx = tid; idx < TW * 128; idx += NTHR) {
        int t = idx >> 7, c = idx & 127;
        float4 v = reinterpret_cast<const float4*>(g_w)[((size_t)wb * TW + t) * 128 + c];
        *reinterpret_cast<float4*>(&w_s[t * WSTR + 4 * c]) = v;
    }
    for (int idx = tid; idx < TO * 128; idx += NTHR) {
        int o = idx >> 7, c = idx & 127;
        float4 v = reinterpret_cast<const float4*>(g_u)[((size_t)ob * TO + o) * 128 + c];
        *reinterpret_cast<float4*>(&uo[o * OSTR + 4 * c]) = v;
    }
    for (int idx = tid; idx < 4 * OSTR; idx += NTHR)
        uo[TO * OSTR + idx] = 0.f;      // rows 36-39 zero (mma N padding)
    __syncthreads();

    // ---------- phase 2: scores via tf32 mma (3-term split) -----------------
    // 16 warps: mt = warp&1 (M tile), ks = warp>>1 (k-slice of 8 k-steps)
    const int wrp  = tid >> 5;
    const int lane = tid & 31;
    if (wrp < 16) {
        const int mt = wrp & 1;
        const int ks = wrp >> 1;
        const int g  = lane >> 2;      // groupID
        const int tg = lane & 3;       // threadID in group

        float c[5][4];
        #pragma unroll
        for (int nt = 0; nt < 5; nt++)
            #pragma unroll
            for (int q = 0; q < 4; q++) c[nt][q] = 0.f;

        const float* wrow0 = w_s + (16 * mt + g) * WSTR;
        const float* wrow1 = wrow0 + 8 * WSTR;

        #pragma unroll 2
        for (int j = 0; j < 8; j++) {
            const int k0 = (ks * 8 + j) * 8;
            float a0 = wrow0[k0 + tg];
            float a1 = wrow1[k0 + tg];
            float a2 = wrow0[k0 + tg + 4];
            float a3 = wrow1[k0 + tg + 4];
            uint32_t ah[4], al[4];
            ah[0] = f2tf(a0); al[0] = __float_as_uint(a0 - __uint_as_float(ah[0]));
            ah[1] = f2tf(a1); al[1] = __float_as_uint(a1 - __uint_as_float(ah[1]));
            ah[2] = f2tf(a2); al[2] = __float_as_uint(a2 - __uint_as_float(ah[2]));
            ah[3] = f2tf(a3); al[3] = __float_as_uint(a3 - __uint_as_float(ah[3]));
            #pragma unroll
            for (int nt = 0; nt < 5; nt++) {
                const float* ur = uo + (8 * nt + g) * OSTR + k0;
                float b0 = ur[tg];
                float b1 = ur[tg + 4];
                uint32_t bh0 = f2tf(b0);
                uint32_t bh1 = f2tf(b1);
                uint32_t bl0 = __float_as_uint(b0 - __uint_as_float(bh0));
                uint32_t bl1 = __float_as_uint(b1 - __uint_as_float(bh1));
                mma_tf32(c[nt], ah, bh0, bh1);
                mma_tf32(c[nt], ah, bl0, bl1);
                mma_tf32(c[nt], al, bh0, bh1);
            }
        }
        // store partials: p2[ks][row 32][col 40]
        float* pp = p2 + ks * 1280 + (16 * mt) * 40;
        #pragma unroll
        for (int nt = 0; nt < 5; nt++) {
            int col = 8 * nt + 2 * tg;
            *reinterpret_cast<float2*>(&pp[g * 40 + col])       = make_float2(c[nt][0], c[nt][1]);
            *reinterpret_cast<float2*>(&pp[(g + 8) * 40 + col]) = make_float2(c[nt][2], c[nt][3]);
        }
    }
    __syncthreads();

    // ---------- phase 3: reduce k-slices + softmax over To=36 ---------------
    const int st = tid / 9, sj = tid % 9;      // valid for tid<288
    float sc[4], ee[4];
    if (tid < 288) {
        #pragma unroll
        for (int q = 0; q < 4; q++) {
            int col = 4 * sj + q;
            float s = 0.f;
            #pragma unroll
            for (int ks = 0; ks < 8; ks++) s += p2[ks * 1280 + st * 40 + col];
            sc[q] = s * SCALE;
        }
        pmax[tid] = fmaxf(fmaxf(sc[0], sc[1]), fmaxf(sc[2], sc[3]));
    }
    __syncthreads();
    if (tid < 32) {
        float m = pmax[tid * 9];
        #pragma unroll
        for (int k = 1; k < 9; k++) m = fmaxf(m, pmax[tid * 9 + k]);
        rowmax[tid] = m;
    }
    __syncthreads();
    if (tid < 288) {
        float m = rowmax[st];
        float s = 0.f;
        #pragma unroll
        for (int q = 0; q < 4; q++) { ee[q] = expf(sc[q] - m); s += ee[q]; }
        psum[tid] = s;
    }
    __syncthreads();
    if (tid < 32) {
        float s = 0.f;
        #pragma unroll
        for (int k = 0; k < 9; k++) s += psum[tid * 9 + k];
        rowinv[tid] = 1.f / s;
    }
    __syncthreads();
    if (tid < 288) {
        float inv = rowinv[st];
        #pragma unroll
        for (int q = 0; q < 4; q++) {
            float a = ee[q] * inv;
            int idx = st * TO + 4 * sj + q;
            att_cs[1 + idx] = a;
            att_al[idx]     = a;
        }
    }
    __syncthreads();

    // ---------- att store (shifted float4) + phase 4a: o tile (shift +1) ----
    {
        const size_t ab = (size_t)blk * (TW * TO);
        if (tid < 287) {
            float4 v = *reinterpret_cast<const float4*>(&att_cs[4 + 4 * tid]);
            *reinterpret_cast<float4*>(&out_att[ab + 3 + 4 * tid]) = v;
        } else if (tid == 287) {
            out_att[ab + 0]    = att_cs[1];
            out_att[ab + 1]    = att_cs[2];
            out_att[ab + 2]    = att_cs[3];
            out_att[ab + 1151] = att_cs[1152];
        }
    }
    for (int task = tid; task < TO * 127; task += NTHR) {
        int o = task / 127, k = task % 127;
        const float* gr = g_o + ((size_t)ob * TO + o) * 512;
        float4 A  = *reinterpret_cast<const float4*>(&gr[4 * k]);
        float4 Bv = *reinterpret_cast<const float4*>(&gr[4 * k + 4]);
        *reinterpret_cast<float4*>(&uo[o * OSTR + 4 + 4 * k]) =
            make_float4(A.w, Bv.x, Bv.y, Bv.z);
    }
    if (tid < 144) {
        int o = tid / 4, e = tid % 4;
        const float* gr = g_o + ((size_t)ob * TO + o) * 512;
        if (e < 3) uo[o * OSTR + 1 + e] = gr[e];
        else       uo[o * OSTR + 512]   = gr[511];
    }
    __syncthreads();

    // ---------- phase 4b: att_V_o, o-outer, vectorized att staging ----------
    {
        const int tg4 = tid / 72;          // t = 4*tg4 + i
        const int jj  = tid % 72;
        const bool have2 = (jj <= 54);     // k1 = jj+72 <= 126 valid
        const int k0 = jj;
        const int k1 = have2 ? (jj + 72) : 126;

        const float* ow0 = &uo[4 + 4 * k0];
        const float* ow1 = &uo[4 + 4 * k1];
        const float* attp = att_al + (tg4 * 4) * TO;

        ull a0[4][2], a1[4][2];
        #pragma unroll
        for (int i = 0; i < 4; i++) {
            a0[i][0] = a0[i][1] = 0ULL;
            a1[i][0] = a1[i][1] = 0ULL;
        }

        F4U avv[4];
        #pragma unroll 4
        for (int o = 0; o < TO; o++) {
            if ((o & 3) == 0) {
                #pragma unroll
                for (int i = 0; i < 4; i++)
                    avv[i].f = *reinterpret_cast<const float4*>(&attp[i * TO + o]);
            }
            F4U ov0; ov0.f = *reinterpret_cast<const float4*>(&ow0[o * OSTR]);
            F4U ov1; ov1.f = *reinterpret_cast<const float4*>(&ow1[o * OSTR]);
            #pragma unroll
            for (int i = 0; i < 4; i++) {
                ull aa = pack2(avv[i].s[o & 3]);
                fma2(a0[i][0], aa, ov0.u[0]);
                fma2(a0[i][1], aa, ov0.u[1]);
                fma2(a1[i][0], aa, ov1.u[0]);
                fma2(a1[i][1], aa, ov1.u[1]);
            }
        }

        #pragma unroll
        for (int i = 0; i < 4; i++) {
            const int t = 4 * tg4 + i;
            const size_t tb = ((size_t)blk * TW + t) * DD;
            float lg;
            {
                F4U av; av.u[0] = a0[i][0]; av.u[1] = a0[i][1];
                *reinterpret_cast<float4*>(&out_avo[tb + 3 + 4 * k0]) = av.f;
                F4U wA; wA.f = *reinterpret_cast<const float4*>(&w_s[t * WSTR + 4 * k0]);
                F4U wB; wB.f = *reinterpret_cast<const float4*>(&w_s[t * WSTR + 4 * k0 + 4]);
                lg = av.s[0] * wA.s[3] + av.s[1] * wB.s[0]
                   + av.s[2] * wB.s[1] + av.s[3] * wB.s[2];
            }
            if (have2) {
                F4U av; av.u[0] = a1[i][0]; av.u[1] = a1[i][1];
                *reinterpret_cast<float4*>(&out_avo[tb + 3 + 4 * k1]) = av.f;
                F4U wA; wA.f = *reinterpret_cast<const float4*>(&w_s[t * WSTR + 4 * k1]);
                F4U wB; wB.f = *reinterpret_cast<const float4*>(&w_s[t * WSTR + 4 * k1 + 4]);
                lg += av.s[0] * wA.s[3] + av.s[1] * wB.s[0]
                    + av.s[2] * wB.s[1] + av.s[3] * wB.s[2];
            }
            lgp[t * 72 + jj] = lg;
        }
    }
    // edge columns d in {0,1,2,511} for every t row
    if (tid < 128) {
        int t = tid / 4, e = tid % 4;
        int d    = (e < 3) ? e        : 511;
        int soff = (e < 3) ? (1 + e)  : 512;
        float acc = 0.f;
        #pragma unroll 4
        for (int o = 0; o < TO; o++)
            acc += att_al[t * TO + o] * uo[o * OSTR + soff];
        out_avo[((size_t)blk * TW + t) * DD + d] = acc;
        lgp2[tid] = acc * w_s[t * WSTR + d];
    }
    __syncthreads();

    if (tid < 32) {
        float s = 0.f;
        #pragma unroll
        for (int k = 0; k < 72; k++) s += lgp[tid * 72 + k];
        #pragma unroll
        for (int e = 0; e < 4; e++)  s += lgp2[tid * 4 + e];
        g_logits[(wb * TW + tid) * BO + ob] = s;
    }
}

// log-softmax over Bo + masked diagonal accumulation, one block per wb
__global__ void cap_loss1(const int* __restrict__ g_mask)
{
    const int wb   = blockIdx.x;
    const int wid  = threadIdx.x >> 5;
    const int lane = threadIdx.x & 31;
    __shared__ float warp_part[8];

    float keepl = 1.f - (float)g_mask[wb * TW + lane];
    float nk = keepl;
    #pragma unroll
    for (int s = 16; s; s >>= 1) nk += __shfl_xor_sync(0xffffffffu, nk, s);

    float acc = 0.f;
    #pragma unroll
    for (int k = 0; k < 4; k++) {
        int t = wid + 8 * k;
        const float* row = g_logits + (wb * TW + t) * BO;
        float v0 = row[lane], v1 = row[lane + 32];
        float m = fmaxf(v0, v1);
        #pragma unroll
        for (int s = 16; s; s >>= 1) m = fmaxf(m, __shfl_xor_sync(0xffffffffu, m, s));
        float e = expf(v0 - m) + expf(v1 - m);
        #pragma unroll
        for (int s = 16; s; s >>= 1) e += __shfl_xor_sync(0xffffffffu, e, s);
        float lse = m + logf(e);
        float dv = (wb < 32) ? __shfl_sync(0xffffffffu, v0, wb)
                             : __shfl_sync(0xffffffffu, v1, wb - 32);
        float kt = 1.f - (float)g_mask[wb * TW + t];
        acc += kt * (dv - lse);
    }
    if (lane == 0) warp_part[wid] = acc;
    __syncthreads();
    if (threadIdx.x == 0) {
        float s = 0.f;
        #pragma unroll
        for (int k = 0; k < 8; k++) s += warp_part[k];
        g_partial[wb] = s / (nk + 1e-6f);
    }
}

__global__ void cap_loss2(float* __restrict__ out)
{
    __shared__ float sh[64];
    sh[threadIdx.x] = g_partial[threadIdx.x];
    __syncthreads();
    if (threadIdx.x == 0) {
        float s = 0.f;
        #pragma unroll
        for (int k = 0; k < 64; k++) s += sh[k];
        out[0] = -s / 64.f;
    }
}

extern "C" void kernel_launch(void* const* d_in, const int* in_sizes, int n_in,
                              void* d_out, int out_size)
{
    const float* g_o    = (const float*)d_in[0];
    const float* g_u    = (const float*)d_in[1];
    const float* g_w    = (const float*)d_in[2];
    const int*   g_mask = (const int*)d_in[3];

    float* out     = (float*)d_out;
    float* out_att = out + 1;
    float* out_avo = out_att + (size_t)BW * BO * TW * TO;

    const size_t SMEM_BYTES = (size_t)SMEM_FLOATS * sizeof(float);
    cudaFuncSetAttribute(cap_main, cudaFuncAttributeMaxDynamicSharedMemorySize,
                         (int)SMEM_BYTES);

    dim3 grid(BO, BW);
    cap_main<<<grid, NTHR, SMEM_BYTES>>>(g_o, g_u, g_w, out_att, out_avo);
    cap_loss1<<<BW, 256>>>(g_mask);
    cap_loss2<<<1, 64>>>(out);
}